// round 15
// baseline (speedup 1.0000x reference)
#include <cuda_runtime.h>

#define FULL 0xFFFFFFFFu
typedef unsigned long long ull;

// ---------- packed f32x2 helpers (Blackwell paired-FP32 path) ----------
__device__ __forceinline__ ull pack2(float x, float y) {
    ull r; asm("mov.b64 %0,{%1,%2};" : "=l"(r) : "f"(x), "f"(y)); return r;
}
__device__ __forceinline__ float2 unpack2(ull v) {
    float2 r; asm("mov.b64 {%0,%1},%2;" : "=f"(r.x), "=f"(r.y) : "l"(v)); return r;
}
__device__ __forceinline__ ull swap2(ull v) {              // (x,y) -> (y,x)
    float2 t = unpack2(v); return pack2(t.y, t.x);
}
__device__ __forceinline__ ull f2mul(ull a, ull b) {
    ull d; asm("mul.rn.f32x2 %0,%1,%2;" : "=l"(d) : "l"(a), "l"(b)); return d;
}
__device__ __forceinline__ ull f2fma(ull a, ull b, ull c) {  // a*b + c
    ull d; asm("fma.rn.f32x2 %0,%1,%2,%3;" : "=l"(d) : "l"(a), "l"(b), "l"(c)); return d;
}

__device__ __forceinline__ float2 cmul(float2 a, float2 b) {
    return make_float2(fmaf(a.x, b.x, -a.y * b.y), fmaf(a.x, b.y, a.y * b.x));
}

// Column 0 of RZ(phi)*RY(pt)*RX(eta) applied to |0>.
__device__ __forceinline__ void wire_u(float pt, float eta, float phi,
                                       float2& u0, float2& u1) {
    float se, ce, sy, cy, sz, cz;
    __sincosf(0.5f * eta, &se, &ce);
    __sincosf(0.5f * pt, &sy, &cy);
    __sincosf(0.5f * phi, &sz, &cz);
    float2 b0 = make_float2(cy * ce, sy * se);
    float2 b1 = make_float2(sy * ce, -cy * se);
    u0 = cmul(make_float2(cz, -sz), b0);
    u1 = cmul(make_float2(cz, sz), b1);
}

// width-16 broadcast of a float2 held lane-wise
__device__ __forceinline__ float2 bc16(float vx, float vy, int src) {
    float2 r;
    r.x = __shfl_sync(FULL, vx, src, 16);
    r.y = __shfl_sync(FULL, vy, src, 16);
    return r;
}

// ---------- gate passes over compile-time register subsets ----------
// Lane-wire RY on registers {START + i*STEP : i < CNT}: a[r] += t2 * shfl(a[r]).
template<int START, int STEP, int CNT>
__device__ __forceinline__ void lane_pass(ull (&a)[64], int mb, ull t2) {
#pragma unroll
    for (int i = 0; i < CNT; i++) {
        int r = START + i * STEP;
        ull p = __shfl_xor_sync(FULL, a[r], mb);
        a[r] = f2fma(t2, p, a[r]);
    }
}

// Register-wire RY (mask M < 32) on the half [R0, R0+32).
template<int R0, int M>
__device__ __forceinline__ void reg_pass(ull (&a)[64], ull tq, ull ntq) {
#pragma unroll
    for (int r = R0; r < R0 + 32; r++) {
        if (!(r & M)) {
            int r1 = r | M;
            ull a0 = a[r];
            a[r]  = f2fma(ntq, a[r1], a0);
            a[r1] = f2fma(tq, a0, a[r1]);
        }
    }
}

// Register-wire RY with mask 32 (pairs (r, r+32)) restricted to r parity START.
template<int START>
__device__ __forceinline__ void reg0_pass(ull (&a)[64], ull tq, ull ntq) {
#pragma unroll
    for (int r = START; r < 32; r += 2) {
        int r1 = r + 32;
        ull a0 = a[r];
        a[r]  = f2fma(ntq, a[r1], a0);
        a[r1] = f2fma(tq, a0, a[r1]);
    }
}

// 4-qubit QAE block (ele / mu): latent=[0,1], trash=[2,3], depth=1.
__device__ __forceinline__ void sim4(const float* __restrict__ xr,
                                     int pt_off, int eta_off, int phi_off,
                                     const float* __restrict__ w,
                                     float& o0, float& o1) {
    float2 u0[4], u1[4];
#pragma unroll
    for (int k = 0; k < 4; k++)
        wire_u(xr[pt_off + k], xr[eta_off + k], xr[phi_off + k], u0[k], u1[k]);

    float2 a[16];
    a[0] = make_float2(1.f, 0.f);
#pragma unroll
    for (int j = 0; j < 4; j++) {
        int wk = 3 - j;
#pragma unroll
        for (int t = 0; t < (1 << j); t++) {
            a[t + (1 << j)] = cmul(a[t], u1[wk]);
            a[t]            = cmul(a[t], u0[wk]);
        }
    }
    // perm1: bits {3,2} ^= parity(bits {1,0})
    {
        float2 t;
        t = a[1];  a[1]  = a[13]; a[13] = t;
        t = a[2];  a[2]  = a[14]; a[14] = t;
        t = a[5];  a[5]  = a[9];  a[9]  = t;
        t = a[6];  a[6]  = a[10]; a[10] = t;
    }
    float sc = 1.f;
#pragma unroll
    for (int k = 0; k < 4; k++) {
        float s, c;
        __sincosf(0.5f * w[k], &s, &c);
        float tau = __fdividef(s, c);
        sc *= c;
        int m = 1 << (3 - k);
#pragma unroll
        for (int i = 0; i < 16; i++) {
            if (!(i & m)) {
                int i1 = i | m;
                float2 a0 = a[i], a1v = a[i1];
                a[i]  = make_float2(fmaf(-tau, a1v.x, a0.x), fmaf(-tau, a1v.y, a0.y));
                a[i1] = make_float2(fmaf(tau, a0.x, a1v.x), fmaf(tau, a0.y, a1v.y));
            }
        }
    }
    // perm2: bits {1,0} ^= parity(bits {3,2})
    {
        float2 t;
        t = a[4]; a[4] = a[7];  a[7]  = t;
        t = a[5]; a[5] = a[6];  a[6]  = t;
        t = a[8]; a[8] = a[11]; a[11] = t;
        t = a[9]; a[9] = a[10]; a[10] = t;
    }
    float r0 = 0.f, r1 = 0.f;
#pragma unroll
    for (int i = 0; i < 16; i++) {
        float p = fmaf(a[i].x, a[i].x, a[i].y * a[i].y);
        r0 += ((i >> 1) & 1) ? -p : p;
        r1 += (i & 1) ? -p : p;
    }
    float sc2 = sc * sc;
    o0 = r0 * sc2;
    o1 = r1 * sc2;
}

__global__ __launch_bounds__(32, 12)
void qae_kernel(const float* __restrict__ x,
                const float* __restrict__ met_w,
                const float* __restrict__ ele_w,
                const float* __restrict__ mu_w,
                const float* __restrict__ jet_w,
                float* __restrict__ out,
                int B, int nJetBlocks) {
    __shared__ float s_tau[40];
    __shared__ float s_scale;

    if ((int)blockIdx.x < nJetBlocks) {
        // ================= jet: 2 events per warp, n=10 qubits =================
        // One warp per block. Amplitude index (10 bits): lane bits 0..3 (sub) =
        // trash wires 9..6; register bits r0..r5 = latent wires 5..0. Lane bit 4
        // selects the event.
        //
        // Within a depth all 10 RY gates commute. They are emitted as pairs of
        // elementwise-INDEPENDENT passes — a lane gate (SHFL) on one register
        // subset alongside a register gate (FMA) on the disjoint subset — so
        // the MIO and FMA pipes are co-fed within a single warp:
        //   L6/L7/L8 paired with R1/R2/R3 via the bit-5 half split;
        //   L9 paired with R0 (mask 32) via the bit-0 parity split;
        //   R4, R5 trail (unpaired).
        int warpId = blockIdx.x;
        int lane = threadIdx.x & 31;
        int sub  = lane & 15;
        int half = lane >> 4;
        int event = warpId * 2 + half;
        int evc = event < B ? event : B - 1;        // clamp for odd B
        const float* xr = x + (size_t)evc * 56;

        // Per-wire encoding column: lanes sub 0..9 of each half compute; values
        // broadcast on demand via width-16 shfl. (tau-free prologue)
        int kk = sub < 10 ? sub : 0;
        float2 myu0, myu1;
        wire_u(xr[26 + kk], xr[36 + kk], xr[46 + kk], myu0, myu1);

        // Lane-bit part of the tensor product: sub bit m <-> trash wire 9-m.
        float2 pl = make_float2(1.f, 0.f);
#pragma unroll
        for (int m = 0; m < 4; m++) {
            int w = 9 - m;
            float2 b0 = bc16(myu0.x, myu0.y, w);
            float2 b1 = bc16(myu1.x, myu1.y, w);
            float2 sel = ((sub >> m) & 1) ? b1 : b0;
            pl = cmul(pl, sel);
        }

        // This warp computes the 40 jet taus + (prod cos)^2 into shared memory.
        {
            float c_all;
            {
                float s, c; __sincosf(0.5f * jet_w[lane], &s, &c);
                s_tau[lane] = __fdividef(s, c);
                c_all = c;
            }
            if (lane < 8) {
                float s, c; __sincosf(0.5f * jet_w[32 + lane], &s, &c);
                s_tau[32 + lane] = __fdividef(s, c);
                c_all *= c;
            }
#pragma unroll
            for (int off = 16; off >= 1; off >>= 1)
                c_all *= __shfl_xor_sync(FULL, c_all, off);
            if (lane == 0) s_scale = c_all * c_all;
        }
        __syncwarp();

        bool p1 = (__popc(sub) & 1) != 0;   // parity of trash bits

        // Register-bit part via doubling: reg bit j <-> latent wire 5-j.
        // Folds: (a) depth-0 perm1 -> factor-role swap when p1;
        //        (b) depth-0 latent RYs -> factor rotation with sign s.
        ull a[64];
        a[0] = pack2(pl.x, pl.y);
#pragma unroll
        for (int j = 0; j < 6; j++) {
            int w = 5 - j;
            float2 b0 = bc16(myu0.x, myu0.y, w);
            float2 b1 = bc16(myu1.x, myu1.y, w);
            float2 f0 = p1 ? b1 : b0;
            float2 f1 = p1 ? b0 : b1;
            float st = p1 ? s_tau[w] : -s_tau[w];
            float2 g0 = make_float2(fmaf(st, f1.x, f0.x), fmaf(st, f1.y, f0.y));
            float2 g1 = make_float2(fmaf(-st, f0.x, f1.x), fmaf(-st, f0.y, f1.y));
            ull g0R = pack2(g0.x, g0.x), g0I = pack2(-g0.y, g0.y);
            ull g1R = pack2(g1.x, g1.x), g1I = pack2(-g1.y, g1.y);
#pragma unroll
            for (int t = 0; t < (1 << j); t++) {
                ull at = a[t];
                ull sw = swap2(at);
                a[t + (1 << j)] = f2fma(sw, g1I, f2mul(at, g1R));
                a[t]            = f2fma(sw, g0I, f2mul(at, g0R));
            }
        }

        // Depth-0 lane gates (trash wires 6..9), then depth-0 perm2.
#pragma unroll
        for (int k = 6; k < 10; k++) {
            int mb = 1 << (9 - k);
            float tau = s_tau[k];
            float tt = (sub & mb) ? tau : -tau;
            ull t2 = pack2(tt, tt);
            lane_pass<0, 1, 64>(a, mb, t2);
        }
#pragma unroll
        for (int r = 0; r < 64; r++) {
            if (__popc(r) & 1)
                a[r] = __shfl_xor_sync(FULL, a[r], 15);
        }

        // Depths 1..3: perm1, co-scheduled gate passes, perm2 (folded at d=3).
#pragma unroll 1
        for (int d = 1; d < 4; d++) {
            const float* td = &s_tau[d * 10];
            // perm1: flip all 6 register (latent) bits if p1.
#pragma unroll
            for (int r = 0; r < 32; r++) {
                ull t0 = a[r], t1 = a[63 - r];
                a[r]      = p1 ? t1 : t0;
                a[63 - r] = p1 ? t0 : t1;
            }
            {   // L6 (mb=8) || R1 (m=16), half split
                float tA = td[6]; float tt = (sub & 8) ? tA : -tA;
                ull tL = pack2(tt, tt);
                float tB = td[1]; ull q = pack2(tB, tB), nq = pack2(-tB, -tB);
                lane_pass<32, 1, 32>(a, 8, tL); reg_pass<0, 16>(a, q, nq);
                lane_pass<0, 1, 32>(a, 8, tL);  reg_pass<32, 16>(a, q, nq);
            }
            {   // L7 (mb=4) || R2 (m=8), half split
                float tA = td[7]; float tt = (sub & 4) ? tA : -tA;
                ull tL = pack2(tt, tt);
                float tB = td[2]; ull q = pack2(tB, tB), nq = pack2(-tB, -tB);
                lane_pass<32, 1, 32>(a, 4, tL); reg_pass<0, 8>(a, q, nq);
                lane_pass<0, 1, 32>(a, 4, tL);  reg_pass<32, 8>(a, q, nq);
            }
            {   // L8 (mb=2) || R3 (m=4), half split
                float tA = td[8]; float tt = (sub & 2) ? tA : -tA;
                ull tL = pack2(tt, tt);
                float tB = td[3]; ull q = pack2(tB, tB), nq = pack2(-tB, -tB);
                lane_pass<32, 1, 32>(a, 2, tL); reg_pass<0, 4>(a, q, nq);
                lane_pass<0, 1, 32>(a, 2, tL);  reg_pass<32, 4>(a, q, nq);
            }
            {   // L9 (mb=1) || R0 (m=32), parity split (R0 pairs preserve bit 0)
                float tA = td[9]; float tt = (sub & 1) ? tA : -tA;
                ull tL = pack2(tt, tt);
                float tB = td[0]; ull q = pack2(tB, tB), nq = pack2(-tB, -tB);
                lane_pass<1, 2, 32>(a, 1, tL); reg0_pass<0>(a, q, nq);
                lane_pass<0, 2, 32>(a, 1, tL); reg0_pass<1>(a, q, nq);
            }
            {   // trailing R4 (m=2), R5 (m=1)
                float t4 = td[4]; ull q4 = pack2(t4, t4), nq4 = pack2(-t4, -t4);
                float t5 = td[5]; ull q5 = pack2(t5, t5), nq5 = pack2(-t5, -t5);
                reg_pass<0, 2>(a, q4, nq4);  reg_pass<32, 2>(a, q4, nq4);
                reg_pass<0, 1>(a, q5, nq5);  reg_pass<32, 1>(a, q5, nq5);
            }
            // perm2: flip trash (lane) bits where popc(r) odd. Skipped on the
            // final depth (folded into the <Z> sign as S_even - S_odd).
            if (d != 3) {
#pragma unroll
                for (int r = 0; r < 64; r++) {
                    if (__popc(r) & 1)
                        a[r] = __shfl_xor_sync(FULL, a[r], 15);
                }
            }
        }

        // <Z> on trash wires 6..9 (sub bits 3..0), final perm2 + global scale
        // absorbed: Z_b = sign_b(sub) * (S_even - S_odd) * (prod cos)^2.
        ull ae0 = pack2(0.f, 0.f), ae1 = pack2(0.f, 0.f);
        ull ao0 = pack2(0.f, 0.f), ao1 = pack2(0.f, 0.f);
#pragma unroll
        for (int r = 0; r < 64; r += 2) {
            if (__popc(r) & 1) ao0 = f2fma(a[r], a[r], ao0);
            else               ae0 = f2fma(a[r], a[r], ae0);
            if (__popc(r + 1) & 1) ao1 = f2fma(a[r + 1], a[r + 1], ao1);
            else                   ae1 = f2fma(a[r + 1], a[r + 1], ae1);
        }
        float2 fe0 = unpack2(ae0), fe1 = unpack2(ae1);
        float2 fo0 = unpack2(ao0), fo1 = unpack2(ao1);
        float sd = ((fe0.x + fe0.y + fe1.x + fe1.y)
                  - (fo0.x + fo0.y + fo1.x + fo1.y)) * s_scale;

        // Signed Walsh butterfly over the 4 sub bits: after 4 levels, lane s
        // holds sum_t (-1)^{popc(s&t)} sd(t); lanes s = 1<<bit carry <Z>.
#pragma unroll
        for (int off = 1; off <= 8; off <<= 1) {
            float p = __shfl_xor_sync(FULL, sd, off);
            sd = (sub & off) ? (p - sd) : (sd + p);
        }
        if (__popc(sub) == 1 && event < B) {
            int bit = 31 - __clz(sub);       // sub = 1<<bit; output j = 3-bit
            out[(size_t)5 * B + (size_t)event * 4 + (3 - bit)] = sd;
        }
    } else {
        // ---------------- met + ele + mu: one thread per event ----------------
        int e = (blockIdx.x - nJetBlocks) * 32 + threadIdx.x;
        if (e >= B) return;
        const float* xr = x + (size_t)e * 56;

        {   // met (n=1): <Z> = cos(w)cos(pt) - sin(w)sin(pt)cos(phi)
            float sw, cw, sp, cp;
            __sincosf(met_w[0], &sw, &cw);
            __sincosf(xr[0], &sp, &cp);
            float cf = __cosf(xr[1]);
            out[e] = cw * cp - sw * sp * cf;
        }
        float o0, o1;
        sim4(xr, 2, 6, 10, ele_w, o0, o1);
        out[(size_t)B + (size_t)e * 2 + 0] = o0;
        out[(size_t)B + (size_t)e * 2 + 1] = o1;
        sim4(xr, 14, 18, 22, mu_w, o0, o1);
        out[(size_t)3 * B + (size_t)e * 2 + 0] = o0;
        out[(size_t)3 * B + (size_t)e * 2 + 1] = o1;
    }
}

extern "C" void kernel_launch(void* const* d_in, const int* in_sizes, int n_in,
                              void* d_out, int out_size) {
    const float* x     = (const float*)d_in[0];
    const float* met_w = (const float*)d_in[1];
    const float* ele_w = (const float*)d_in[2];
    const float* mu_w  = (const float*)d_in[3];
    const float* jet_w = (const float*)d_in[4];
    int B = in_sizes[0] / 56;
    int nJetBlocks = (B + 1) / 2;          // 1 warp/block, 2 events/warp
    int nSmallBlocks = (B + 31) / 32;      // 1 thread/event for met/ele/mu
    qae_kernel<<<nJetBlocks + nSmallBlocks, 32>>>(
        x, met_w, ele_w, mu_w, jet_w, (float*)d_out, B, nJetBlocks);
}

// round 16
// speedup vs baseline: 1.3240x; 1.3240x over previous
#include <cuda_runtime.h>

#define FULL 0xFFFFFFFFu
typedef unsigned long long ull;

// ---------- packed f32x2 helpers (Blackwell paired-FP32 path) ----------
__device__ __forceinline__ ull pack2(float x, float y) {
    ull r; asm("mov.b64 %0,{%1,%2};" : "=l"(r) : "f"(x), "f"(y)); return r;
}
__device__ __forceinline__ float2 unpack2(ull v) {
    float2 r; asm("mov.b64 {%0,%1},%2;" : "=f"(r.x), "=f"(r.y) : "l"(v)); return r;
}
__device__ __forceinline__ ull swap2(ull v) {              // (x,y) -> (y,x)
    float2 t = unpack2(v); return pack2(t.y, t.x);
}
__device__ __forceinline__ ull f2mul(ull a, ull b) {
    ull d; asm("mul.rn.f32x2 %0,%1,%2;" : "=l"(d) : "l"(a), "l"(b)); return d;
}
__device__ __forceinline__ ull f2fma(ull a, ull b, ull c) {  // a*b + c
    ull d; asm("fma.rn.f32x2 %0,%1,%2,%3;" : "=l"(d) : "l"(a), "l"(b), "l"(c)); return d;
}

__device__ __forceinline__ float2 cmul(float2 a, float2 b) {
    return make_float2(fmaf(a.x, b.x, -a.y * b.y), fmaf(a.x, b.y, a.y * b.x));
}

// Column 0 of RZ(phi)*RY(pt)*RX(eta) applied to |0>.
__device__ __forceinline__ void wire_u(float pt, float eta, float phi,
                                       float2& u0, float2& u1) {
    float se, ce, sy, cy, sz, cz;
    __sincosf(0.5f * eta, &se, &ce);
    __sincosf(0.5f * pt, &sy, &cy);
    __sincosf(0.5f * phi, &sz, &cz);
    float2 b0 = make_float2(cy * ce, sy * se);
    float2 b1 = make_float2(sy * ce, -cy * se);
    u0 = cmul(make_float2(cz, -sz), b0);
    u1 = cmul(make_float2(cz, sz), b1);
}

// width-16 broadcast of a float2 held lane-wise
__device__ __forceinline__ float2 bc16(float vx, float vy, int src) {
    float2 r;
    r.x = __shfl_sync(FULL, vx, src, 16);
    r.y = __shfl_sync(FULL, vy, src, 16);
    return r;
}

// 4-qubit QAE block (ele / mu): latent=[0,1], trash=[2,3], depth=1.
__device__ __forceinline__ void sim4(const float* __restrict__ xr,
                                     int pt_off, int eta_off, int phi_off,
                                     const float* __restrict__ w,
                                     float& o0, float& o1) {
    float2 u0[4], u1[4];
#pragma unroll
    for (int k = 0; k < 4; k++)
        wire_u(xr[pt_off + k], xr[eta_off + k], xr[phi_off + k], u0[k], u1[k]);

    float2 a[16];
    a[0] = make_float2(1.f, 0.f);
#pragma unroll
    for (int j = 0; j < 4; j++) {
        int wk = 3 - j;
#pragma unroll
        for (int t = 0; t < (1 << j); t++) {
            a[t + (1 << j)] = cmul(a[t], u1[wk]);
            a[t]            = cmul(a[t], u0[wk]);
        }
    }
    // perm1: bits {3,2} ^= parity(bits {1,0})
    {
        float2 t;
        t = a[1];  a[1]  = a[13]; a[13] = t;
        t = a[2];  a[2]  = a[14]; a[14] = t;
        t = a[5];  a[5]  = a[9];  a[9]  = t;
        t = a[6];  a[6]  = a[10]; a[10] = t;
    }
    float sc = 1.f;
#pragma unroll
    for (int k = 0; k < 4; k++) {
        float s, c;
        __sincosf(0.5f * w[k], &s, &c);
        float tau = __fdividef(s, c);
        sc *= c;
        int m = 1 << (3 - k);
#pragma unroll
        for (int i = 0; i < 16; i++) {
            if (!(i & m)) {
                int i1 = i | m;
                float2 a0 = a[i], a1v = a[i1];
                a[i]  = make_float2(fmaf(-tau, a1v.x, a0.x), fmaf(-tau, a1v.y, a0.y));
                a[i1] = make_float2(fmaf(tau, a0.x, a1v.x), fmaf(tau, a0.y, a1v.y));
            }
        }
    }
    // perm2: bits {1,0} ^= parity(bits {3,2})
    {
        float2 t;
        t = a[4]; a[4] = a[7];  a[7]  = t;
        t = a[5]; a[5] = a[6];  a[6]  = t;
        t = a[8]; a[8] = a[11]; a[11] = t;
        t = a[9]; a[9] = a[10]; a[10] = t;
    }
    float r0 = 0.f, r1 = 0.f;
#pragma unroll
    for (int i = 0; i < 16; i++) {
        float p = fmaf(a[i].x, a[i].x, a[i].y * a[i].y);
        r0 += ((i >> 1) & 1) ? -p : p;
        r1 += (i & 1) ? -p : p;
    }
    float sc2 = sc * sc;
    o0 = r0 * sc2;
    o1 = r1 * sc2;
}

__global__ __launch_bounds__(32, 12)
void qae_kernel(const float* __restrict__ x,
                const float* __restrict__ met_w,
                const float* __restrict__ ele_w,
                const float* __restrict__ mu_w,
                const float* __restrict__ jet_w,
                float* __restrict__ out,
                int B, int nJetBlocks) {
    __shared__ float s_tau[40];
    __shared__ float s_scale;

    if ((int)blockIdx.x < nJetBlocks) {
        // ================= jet: 2 events per warp, n=10 qubits =================
        // One warp per block. Amplitude index (10 bits): lane bits 0..3 (sub) =
        // trash wires 9..6; register bits r0..r5 = latent wires 5..0. Lane bit 4
        // selects the event.
        //
        // RANK-2 DEPTH-0: after encoding + (perm1_d0 + latent-RY fold), the
        // state is a(sub,r) = pE(sub)*F(r) + pO(sub)*F(63^r), where F uses the
        // p1=0 factor roles (identity F_1(r) = F_0(63^r) holds because the
        // p1-swapped factors satisfy g0^1 = g1^0, g1^1 = g0^0), and pE/pO are
        // the even/odd-trash-parity lane products. The 4 depth-0 trash RYs act
        // only on the lane functions -> evolve the 2-component (A,B) object
        // (8 ull-shfl total instead of 256). Depth-0 perm2 folds into A15/B15;
        // depth-1 perm1 folds into the coefficient select at materialization.
        int warpId = blockIdx.x;
        int lane = threadIdx.x & 31;
        int sub  = lane & 15;
        int half = lane >> 4;
        int event = warpId * 2 + half;
        int evc = event < B ? event : B - 1;        // clamp for odd B
        const float* xr = x + (size_t)evc * 56;

        // Per-wire encoding column: lanes sub 0..9 of each half compute; values
        // broadcast on demand via width-16 shfl.
        int kk = sub < 10 ? sub : 0;
        float2 myu0, myu1;
        wire_u(xr[26 + kk], xr[36 + kk], xr[46 + kk], myu0, myu1);

        // Lane-bit part of the tensor product: sub bit m <-> trash wire 9-m.
        float2 pl = make_float2(1.f, 0.f);
#pragma unroll
        for (int m = 0; m < 4; m++) {
            int w = 9 - m;
            float2 b0 = bc16(myu0.x, myu0.y, w);
            float2 b1 = bc16(myu1.x, myu1.y, w);
            float2 sel = ((sub >> m) & 1) ? b1 : b0;
            pl = cmul(pl, sel);
        }

        // This warp computes the 40 jet taus + (prod cos)^2 into shared memory.
        {
            float c_all;
            {
                float s, c; __sincosf(0.5f * jet_w[lane], &s, &c);
                s_tau[lane] = __fdividef(s, c);
                c_all = c;
            }
            if (lane < 8) {
                float s, c; __sincosf(0.5f * jet_w[32 + lane], &s, &c);
                s_tau[32 + lane] = __fdividef(s, c);
                c_all *= c;
            }
#pragma unroll
            for (int off = 16; off >= 1; off >>= 1)
                c_all *= __shfl_xor_sync(FULL, c_all, off);
            if (lane == 0) s_scale = c_all * c_all;
        }
        __syncwarp();

        bool p1 = (__popc(sub) & 1) != 0;   // parity of trash bits

        // Register-bit doubling with p1=0 factor roles (LANE-UNIFORM):
        //   g0 = b0 - tau*b1, g1 = b1 + tau*b0  (depth-0 latent RY folded).
        // Produces F(r); the p1=1 branch is recovered later via F(63^r).
        ull a[64];
        a[0] = pack2(1.f, 0.f);
#pragma unroll
        for (int j = 0; j < 6; j++) {
            int w = 5 - j;
            float2 b0 = bc16(myu0.x, myu0.y, w);
            float2 b1 = bc16(myu1.x, myu1.y, w);
            float tau = s_tau[w];
            float2 g0 = make_float2(fmaf(-tau, b1.x, b0.x), fmaf(-tau, b1.y, b0.y));
            float2 g1 = make_float2(fmaf(tau, b0.x, b1.x), fmaf(tau, b0.y, b1.y));
            ull g0R = pack2(g0.x, g0.x), g0I = pack2(-g0.y, g0.y);
            ull g1R = pack2(g1.x, g1.x), g1I = pack2(-g1.y, g1.y);
#pragma unroll
            for (int t = 0; t < (1 << j); t++) {
                ull at = a[t];
                ull sw = swap2(at);
                a[t + (1 << j)] = f2fma(sw, g1I, f2mul(at, g1R));
                a[t]            = f2fma(sw, g0I, f2mul(at, g0R));
            }
        }

        // Depth-0 trash gates on the rank-2 coefficients (A = even-parity lane
        // product, B = odd-parity): 4 gates x 2 components = 8 ull-shfl.
        ull A = p1 ? pack2(0.f, 0.f) : pack2(pl.x, pl.y);
        ull Bc = p1 ? pack2(pl.x, pl.y) : pack2(0.f, 0.f);
#pragma unroll
        for (int k = 6; k < 10; k++) {
            int mb = 1 << (9 - k);
            float tau = s_tau[k];
            float tt = (sub & mb) ? tau : -tau;
            ull t2 = pack2(tt, tt);
            ull pA = __shfl_xor_sync(FULL, A, mb);
            ull pB = __shfl_xor_sync(FULL, Bc, mb);
            A  = f2fma(t2, pA, A);
            Bc = f2fma(t2, pB, Bc);
        }
        // Depth-0 perm2 fold: odd-register-parity elements read coefficients
        // from lane sub^15.
        ull A15 = __shfl_xor_sync(FULL, A, 15);
        ull B15 = __shfl_xor_sync(FULL, Bc, 15);

        // Materialize a(sub,r) = CA*F(r) + CB*F(63-r), in place, pairwise.
        // Coefficient select folds depth-1 perm1 (swap CA/CB when p1) and
        // depth-0 perm2 (use A15/B15 when popc(r) odd). Two parity passes keep
        // only 4 packed constants live (register-pressure law from R13/R15).
#pragma unroll
        for (int q = 0; q < 2; q++) {
            ull Aq = q ? A15 : A;
            ull Bq = q ? B15 : Bc;
            ull CAu = p1 ? Bq : Aq;
            ull CBu = p1 ? Aq : Bq;
            float2 ca = unpack2(CAu), cb = unpack2(CBu);
            ull CAR = pack2(ca.x, ca.x), CAI = pack2(-ca.y, ca.y);
            ull CBR = pack2(cb.x, cb.x), CBI = pack2(-cb.y, cb.y);
#pragma unroll
            for (int r = 0; r < 32; r++) {
                if ((__popc(r) & 1) == q) {
                    int r2 = 63 - r;
                    ull Fr = a[r], Fs = a[r2];
                    ull sFr = swap2(Fr), sFs = swap2(Fs);
                    ull t0 = f2fma(sFr, CAI, f2mul(Fr, CAR));
                    a[r]  = f2fma(sFs, CBI, f2fma(Fs, CBR, t0));
                    ull t1 = f2fma(sFs, CAI, f2mul(Fs, CAR));
                    a[r2] = f2fma(sFr, CBI, f2fma(Fr, CBR, t1));
                }
            }
        }

        // Depths 1..3: gates in interleaved lane/reg order; perm1 of depth 1 is
        // already folded above; perm1 of depths 2,3 physical; perm2 physical
        // except depth 3 (folded into the measurement sign).
        const int korder[10] = {6, 0, 1, 7, 2, 3, 8, 4, 5, 9};
#pragma unroll 1
        for (int d = 1; d < 4; d++) {
            if (d > 1) {   // perm1: flip all 6 register (latent) bits if p1.
#pragma unroll
                for (int r = 0; r < 32; r++) {
                    ull t0 = a[r], t1 = a[63 - r];
                    a[r]      = p1 ? t1 : t0;
                    a[63 - r] = p1 ? t0 : t1;
                }
            }
#pragma unroll
            for (int kq = 0; kq < 10; kq++) {
                int k = korder[kq];
                float tau = s_tau[d * 10 + k];
                if (k < 6) {                     // register bit j = 5-k
                    int m = 1 << (5 - k);
                    ull tq = pack2(tau, tau), ntq = pack2(-tau, -tau);
#pragma unroll
                    for (int r = 0; r < 64; r++) {
                        if (!(r & m)) {
                            int r1 = r | m;
                            ull a0 = a[r];
                            a[r]  = f2fma(ntq, a[r1], a0);
                            a[r1] = f2fma(tq, a0, a[r1]);
                        }
                    }
                } else {                         // lane bit (9-k): shfl pairing
                    int mb = 1 << (9 - k);
                    float tt = (sub & mb) ? tau : -tau;
                    ull t2 = pack2(tt, tt);
#pragma unroll
                    for (int r = 0; r < 64; r++) {
                        ull p = __shfl_xor_sync(FULL, a[r], mb);
                        a[r] = f2fma(t2, p, a[r]);
                    }
                }
            }
            // perm2: flip trash (lane) bits where popc(r) odd. Skipped on the
            // final depth (folded into the <Z> sign as S_even - S_odd).
            if (d != 3) {
#pragma unroll
                for (int r = 0; r < 64; r++) {
                    if (__popc(r) & 1)
                        a[r] = __shfl_xor_sync(FULL, a[r], 15);
                }
            }
        }

        // <Z> on trash wires 6..9 (sub bits 3..0), final perm2 + global scale
        // absorbed: Z_b = sign_b(sub) * (S_even - S_odd) * (prod cos)^2.
        ull ae0 = pack2(0.f, 0.f), ae1 = pack2(0.f, 0.f);
        ull ao0 = pack2(0.f, 0.f), ao1 = pack2(0.f, 0.f);
#pragma unroll
        for (int r = 0; r < 64; r += 2) {
            if (__popc(r) & 1) ao0 = f2fma(a[r], a[r], ao0);
            else               ae0 = f2fma(a[r], a[r], ae0);
            if (__popc(r + 1) & 1) ao1 = f2fma(a[r + 1], a[r + 1], ao1);
            else                   ae1 = f2fma(a[r + 1], a[r + 1], ae1);
        }
        float2 fe0 = unpack2(ae0), fe1 = unpack2(ae1);
        float2 fo0 = unpack2(ao0), fo1 = unpack2(ao1);
        float sd = ((fe0.x + fe0.y + fe1.x + fe1.y)
                  - (fo0.x + fo0.y + fo1.x + fo1.y)) * s_scale;

        // Signed Walsh butterfly over the 4 sub bits: after 4 levels, lane s
        // holds sum_t (-1)^{popc(s&t)} sd(t); lanes s = 1<<bit carry <Z>.
#pragma unroll
        for (int off = 1; off <= 8; off <<= 1) {
            float p = __shfl_xor_sync(FULL, sd, off);
            sd = (sub & off) ? (p - sd) : (sd + p);
        }
        if (__popc(sub) == 1 && event < B) {
            int bit = 31 - __clz(sub);       // sub = 1<<bit; output j = 3-bit
            out[(size_t)5 * B + (size_t)event * 4 + (3 - bit)] = sd;
        }
    } else {
        // ---------------- met + ele + mu: one thread per event ----------------
        int e = (blockIdx.x - nJetBlocks) * 32 + threadIdx.x;
        if (e >= B) return;
        const float* xr = x + (size_t)e * 56;

        {   // met (n=1): <Z> = cos(w)cos(pt) - sin(w)sin(pt)cos(phi)
            float sw, cw, sp, cp;
            __sincosf(met_w[0], &sw, &cw);
            __sincosf(xr[0], &sp, &cp);
            float cf = __cosf(xr[1]);
            out[e] = cw * cp - sw * sp * cf;
        }
        float o0, o1;
        sim4(xr, 2, 6, 10, ele_w, o0, o1);
        out[(size_t)B + (size_t)e * 2 + 0] = o0;
        out[(size_t)B + (size_t)e * 2 + 1] = o1;
        sim4(xr, 14, 18, 22, mu_w, o0, o1);
        out[(size_t)3 * B + (size_t)e * 2 + 0] = o0;
        out[(size_t)3 * B + (size_t)e * 2 + 1] = o1;
    }
}

extern "C" void kernel_launch(void* const* d_in, const int* in_sizes, int n_in,
                              void* d_out, int out_size) {
    const float* x     = (const float*)d_in[0];
    const float* met_w = (const float*)d_in[1];
    const float* ele_w = (const float*)d_in[2];
    const float* mu_w  = (const float*)d_in[3];
    const float* jet_w = (const float*)d_in[4];
    int B = in_sizes[0] / 56;
    int nJetBlocks = (B + 1) / 2;          // 1 warp/block, 2 events/warp
    int nSmallBlocks = (B + 31) / 32;      // 1 thread/event for met/ele/mu
    qae_kernel<<<nJetBlocks + nSmallBlocks, 32>>>(
        x, met_w, ele_w, mu_w, jet_w, (float*)d_out, B, nJetBlocks);
}